// round 7
// baseline (speedup 1.0000x reference)
#include <cuda_runtime.h>
#include <cuda_fp16.h>
#include <math.h>
#include <stdint.h>

#define BB 8
#define CC 256
#define NN 2048

// rn-scaled 2-way fp16 splits, K-contiguous: g_xs[b][n][s*256 + c], s in {0,1}
__device__ __align__(16) __half g_xs[(size_t)BB * NN * 512];
// transposed f32 copy for fuse gathers: g_xt[b][n][c]
__device__ __align__(16) float g_xt[(size_t)BB * NN * CC];
__device__ int g_idx[BB * NN];

// ---------------------------------------------------------------------------
// prep: per token compute rn, write f32 transpose (g_xt) and rn-scaled 2-way
// fp16 splits (g_xs). grid (NN/32, BB), 256 threads.
// ---------------------------------------------------------------------------
__global__ __launch_bounds__(256) void prep_kernel(const float* __restrict__ x) {
    __shared__ __half S[32][520];
    __shared__ float nsum[32][8];
    __shared__ float rns[32];
    int b = blockIdx.y, n0 = blockIdx.x * 32;
    int tid = threadIdx.x, nl = tid & 31, c8 = tid >> 5;
    const float* xp = x + (size_t)b * CC * NN + n0 + nl;

    float v[32];
    float s = 0.f;
#pragma unroll
    for (int cc = 0; cc < 32; ++cc) {
        int c = c8 * 32 + cc;
        v[cc] = xp[(size_t)c * NN];
        s = fmaf(v[cc], v[cc], s);
    }
    nsum[nl][c8] = s;
    __syncthreads();
    if (tid < 32) {
        float t = 0.f;
#pragma unroll
        for (int q = 0; q < 8; ++q) t += nsum[tid][q];
        rns[tid] = rsqrtf(t + (float)CC * 1e-6f);
    }
    __syncthreads();
    float rn = rns[nl];

    float* xt = g_xt + ((size_t)(b * NN + n0 + nl)) * 256 + c8 * 32;
#pragma unroll
    for (int q = 0; q < 8; ++q)
        *(float4*)(xt + q * 4) = make_float4(v[q * 4], v[q * 4 + 1], v[q * 4 + 2], v[q * 4 + 3]);

#pragma unroll
    for (int cc = 0; cc < 32; ++cc) {
        int c = c8 * 32 + cc;
        float f = v[cc] * rn;
        __half h1 = __float2half_rn(f);
        float r1 = f - __half2float(h1);
        __half h2 = __float2half_rn(r1);
        S[nl][c] = h1; S[nl][256 + c] = h2;
    }
    __syncthreads();

    __half* outb = g_xs + ((size_t)(b * NN + n0)) * 512;
#pragma unroll
    for (int r = 0; r < 8; ++r) {
        int idx = tid + r * 256;
        int row = idx >> 6, c16 = idx & 63;
        uint4 val = *(const uint4*)&S[row][c16 * 8];
        *(uint4*)(outb + (size_t)row * 512 + c16 * 8) = val;
    }
}

// ---------------------------------------------------------------------------
// smem map for simargmax (byte offsets; 16B chunk granularity)
// ---------------------------------------------------------------------------
#define ARES_BYTES (2 * 128 * 33 * 16)          // resident A splits 0,1; padded stride 33
#define BOFF       (ARES_BYTES)                 // 135168
#define BSLOT      (128 * 9 * 16)               // 18432: one 128-row B tile, padded stride 9
#define MVOFF      (BOFF + 3 * BSLOT)           // 190464
#define MJOFF      (MVOFF + 512)
#define SMEM_TOTAL (MJOFF + 512)                // 191488

__device__ __forceinline__ void ldsm4(uint32_t* r, uint32_t saddr) {
    asm volatile("ldmatrix.sync.aligned.m8n8.x4.shared.b16 {%0,%1,%2,%3}, [%4];"
                 : "=r"(r[0]), "=r"(r[1]), "=r"(r[2]), "=r"(r[3]) : "r"(saddr));
}
__device__ __forceinline__ void mma16816f(float (&d)[4], const uint32_t (&a)[4],
                                          uint32_t b0, uint32_t b1) {
    asm volatile(
        "mma.sync.aligned.m16n8k16.row.col.f32.f16.f16.f32 "
        "{%0,%1,%2,%3},{%4,%5,%6,%7},{%8,%9},{%0,%1,%2,%3};"
        : "+f"(d[0]), "+f"(d[1]), "+f"(d[2]), "+f"(d[3])
        : "r"(a[0]), "r"(a[1]), "r"(a[2]), "r"(a[3]), "r"(b0), "r"(b1));
}
__device__ __forceinline__ void mma16816h(uint32_t (&d)[2], const uint32_t (&a)[4],
                                          uint32_t b0, uint32_t b1) {
    asm volatile(
        "mma.sync.aligned.m16n8k16.row.col.f16.f16.f16.f16 "
        "{%0,%1},{%2,%3,%4,%5},{%6,%7},{%0,%1};"
        : "+r"(d[0]), "+r"(d[1])
        : "r"(a[0]), "r"(a[1]), "r"(a[2]), "r"(a[3]), "r"(b0), "r"(b1));
}

// async copy of one 128x64-half B tile (tile index t: jt=t>>3, sb=(t&7)>>2, kc=t&3)
__device__ __forceinline__ void cpB(uint32_t smb, const __half* xsb, int t, int tid) {
    int j0 = (t >> 3) * 128, sb = (t >> 2) & 1, kc = t & 3, slot = t % 3;
#pragma unroll
    for (int q = 0; q < 4; ++q) {
        int idx = tid + q * 256;
        int row = idx >> 3, ch = idx & 7;
        uint32_t sa = smb + BOFF + slot * BSLOT + ((row * 9 + ch) << 4);
        const void* ga = xsb + (size_t)(j0 + row) * 512 + sb * 256 + kc * 64 + ch * 8;
        asm volatile("cp.async.cg.shared.global [%0], [%1], 16;" :: "r"(sa), "l"(ga));
    }
}
#define CP_COMMIT() asm volatile("cp.async.commit_group;" ::: "memory")
#define CP_WAIT1()  asm volatile("cp.async.wait_group 1;" ::: "memory")

// ---------------------------------------------------------------------------
// simargmax: emulated-fp32 GEMM, pair (x1,y1) in f32 acc, cross pairs
// (x2,y1)+(x1,y2) in a shared f16 acc. grid (16, BB), 256 threads (4M x 2N).
// 3-stage cp.async ring, one sync per tile, prefetch distance 2.
// ---------------------------------------------------------------------------
__global__ __launch_bounds__(256, 1) void simargmax_kernel() {
    extern __shared__ __align__(1024) char sm[];
    const int b = blockIdx.y, i0 = blockIdx.x * 128;
    const int tid = threadIdx.x, lane = tid & 31, wid = tid >> 5;
    const int wm = wid >> 1, wn = wid & 1;
    const uint32_t smb = (uint32_t)__cvta_generic_to_shared(sm);
    const __half* xsb = g_xs + (size_t)b * NN * 512;

    // resident A: both splits, rows i0..i0+127, full K=256 (32 chunks/row)
#pragma unroll
    for (int r = 0; r < 32; ++r) {
        int idx = tid + r * 256;
        int s   = idx >> 12;
        int row = (idx >> 5) & 127;
        int ch  = idx & 31;
        uint4 v = *(const uint4*)(xsb + (size_t)(i0 + row) * 512 + s * 256 + ch * 8);
        *(uint4*)(sm + ((((s << 7) + row) * 33 + ch) << 4)) = v;
    }

    const int ar0 = wm * 32 + (lane & 15);
    const int akh = lane >> 4;
    const int jr0 = wn * 64 + ((lane >> 4) & 1) * 8 + (lane & 7);
    const int bkh = (lane >> 3) & 1;

    const float NEG = __int_as_float(0xff800000);
    float best[4]; int bidx[4];
#pragma unroll
    for (int s = 0; s < 4; ++s) { best[s] = NEG; bidx[s] = 0; }

    float    acc[2][8][4];
    uint32_t accH[2][8][2];

    // prologue: tiles 0,1 in flight
    cpB(smb, xsb, 0, tid); CP_COMMIT();
    cpB(smb, xsb, 1, tid); CP_COMMIT();
    __syncthreads();   // also covers resident-A visibility

    for (int t = 0; t < 128; ++t) {
        const int itt = t & 7;
        const int sb  = itt >> 2;
        const int kc  = itt & 3;
        const int buf = t % 3;

        if (itt == 0) {
#pragma unroll
            for (int mt = 0; mt < 2; ++mt)
#pragma unroll
                for (int nt = 0; nt < 8; ++nt) {
#pragma unroll
                    for (int rr = 0; rr < 4; ++rr) acc[mt][nt][rr] = 0.f;
                    accH[mt][nt][0] = 0u; accH[mt][nt][1] = 0u;
                }
        }

        CP_WAIT1();            // tile t resident
        __syncthreads();       // visible to all; all readers of slot (t+2)%3 done
        if (t + 2 < 128) cpB(smb, xsb, t + 2, tid);
        CP_COMMIT();

#pragma unroll
        for (int ks = 0; ks < 4; ++ks) {
            uint32_t bf[4][4];
#pragma unroll
            for (int ntp = 0; ntp < 4; ++ntp) {
                uint32_t bd = smb + BOFF + buf * BSLOT +
                    ((((jr0 + ntp * 16) * 9) + ks * 2 + bkh) << 4);
                ldsm4(bf[ntp], bd);
            }
            const int cb = kc * 8 + ks * 2;
            if (sb == 0) {
                // P0: A split0 -> f32 acc
                uint32_t a0[2][4];
#pragma unroll
                for (int mt = 0; mt < 2; ++mt)
                    ldsm4(a0[mt], smb + ((((ar0 + mt * 16) * 33) + cb + akh) << 4));
#pragma unroll
                for (int ntp = 0; ntp < 4; ++ntp) {
                    mma16816f(acc[0][ntp * 2],     a0[0], bf[ntp][0], bf[ntp][1]);
                    mma16816f(acc[0][ntp * 2 + 1], a0[0], bf[ntp][2], bf[ntp][3]);
                    mma16816f(acc[1][ntp * 2],     a0[1], bf[ntp][0], bf[ntp][1]);
                    mma16816f(acc[1][ntp * 2 + 1], a0[1], bf[ntp][2], bf[ntp][3]);
                }
                // P1: A split1 -> f16 acc
                uint32_t a1[2][4];
#pragma unroll
                for (int mt = 0; mt < 2; ++mt)
                    ldsm4(a1[mt], smb + ((((128 + ar0 + mt * 16) * 33) + cb + akh) << 4));
#pragma unroll
                for (int ntp = 0; ntp < 4; ++ntp) {
                    mma16816h(accH[0][ntp * 2],     a1[0], bf[ntp][0], bf[ntp][1]);
                    mma16816h(accH[0][ntp * 2 + 1], a1[0], bf[ntp][2], bf[ntp][3]);
                    mma16816h(accH[1][ntp * 2],     a1[1], bf[ntp][0], bf[ntp][1]);
                    mma16816h(accH[1][ntp * 2 + 1], a1[1], bf[ntp][2], bf[ntp][3]);
                }
            } else {
                // P2: A split0 x B split1 -> f16 acc
                uint32_t a0[2][4];
#pragma unroll
                for (int mt = 0; mt < 2; ++mt)
                    ldsm4(a0[mt], smb + ((((ar0 + mt * 16) * 33) + cb + akh) << 4));
#pragma unroll
                for (int ntp = 0; ntp < 4; ++ntp) {
                    mma16816h(accH[0][ntp * 2],     a0[0], bf[ntp][0], bf[ntp][1]);
                    mma16816h(accH[0][ntp * 2 + 1], a0[0], bf[ntp][2], bf[ntp][3]);
                    mma16816h(accH[1][ntp * 2],     a0[1], bf[ntp][0], bf[ntp][1]);
                    mma16816h(accH[1][ntp * 2 + 1], a0[1], bf[ntp][2], bf[ntp][3]);
                }
            }
        }

        if (itt == 7) {
            // epilogue for jt = t>>3: combine accs, mask diagonal, running argmax
            const int j0 = (t >> 3) * 128;
#pragma unroll
            for (int mt = 0; mt < 2; ++mt)
#pragma unroll
                for (int nt = 0; nt < 8; ++nt)
#pragma unroll
                    for (int rr = 0; rr < 4; ++rr) {
                        int jl = wn * 64 + nt * 8 + (lane & 3) * 2 + (rr & 1);
                        int il = wm * 32 + mt * 16 + (rr >> 1) * 8 + (lane >> 2);
                        __half2 h2 = *(__half2*)&accH[mt][nt][rr >> 1];
                        float cross = (rr & 1) ? __high2float(h2) : __low2float(h2);
                        float v = acc[mt][nt][rr] + cross;
                        if (j0 + jl == i0 + il) v = NEG;
                        int slot = mt * 2 + (rr >> 1);
                        if (v > best[slot]) { best[slot] = v; bidx[slot] = j0 + jl; }
                    }
        }
    }

    // cross-lane (quad) + cross-warp_n reduction; first-index tie-break
    float* Rv = (float*)(sm + MVOFF);
    int*   Rj = (int*)(sm + MJOFF);
#pragma unroll
    for (int slot = 0; slot < 4; ++slot) {
        float v = best[slot]; int j = bidx[slot];
#pragma unroll
        for (int o = 1; o <= 2; o <<= 1) {
            float vo = __shfl_xor_sync(0xffffffffu, v, o);
            int   jo = __shfl_xor_sync(0xffffffffu, j, o);
            if (vo > v || (vo == v && jo < j)) { v = vo; j = jo; }
        }
        best[slot] = v; bidx[slot] = j;
        int row = wm * 32 + (slot >> 1) * 16 + (slot & 1) * 8 + (lane >> 2);
        if (wn == 1 && (lane & 3) == 0) { Rv[row] = v; Rj[row] = j; }
    }
    __syncthreads();
    if (wn == 0 && (lane & 3) == 0) {
#pragma unroll
        for (int slot = 0; slot < 4; ++slot) {
            int row = wm * 32 + (slot >> 1) * 16 + (slot & 1) * 8 + (lane >> 2);
            float v = best[slot]; int j = bidx[slot];
            float vo = Rv[row]; int jo = Rj[row];
            if (vo > v || (vo == v && jo < j)) { v = vo; j = jo; }
            g_idx[b * NN + i0 + row] = j;
        }
    }
}

// ---------------------------------------------------------------------------
// fuse: staged in smem via g_xt; coalesced reads/writes. grid (NN/32, BB), 256 thr.
// ---------------------------------------------------------------------------
#define FS_SF 32896
#define FS_W  65792
#define FS_JI 69888
#define FS_W0 70016
#define FS_W1 70144
#define FS_TOTAL 70272

__global__ __launch_bounds__(256) void fuse_kernel(const float* __restrict__ W,
                                                   float* __restrict__ out) {
    extern __shared__ char fsm[];
    float* Sx  = (float*)fsm;
    float* Sf  = (float*)(fsm + FS_SF);
    float* Wsh = (float*)(fsm + FS_W);
    int*   Ji  = (int*)(fsm + FS_JI);
    float* W0  = (float*)(fsm + FS_W0);
    float* W1  = (float*)(fsm + FS_W1);

    int b = blockIdx.y, n0 = blockIdx.x * 32, tid = threadIdx.x;
    for (int e = tid; e < 1024; e += 256) Wsh[e] = W[e];
    if (tid < 32) Ji[tid] = g_idx[b * NN + n0 + tid];
    __syncthreads();

    const float* xtb = g_xt + (size_t)b * NN * 256;
    {
        int r = tid >> 3, p = tid & 7;
        const float* srcx = xtb + (size_t)(n0 + r) * 256 + p * 32;
        const float* srcf = xtb + (size_t)Ji[r] * 256 + p * 32;
#pragma unroll
        for (int q = 0; q < 8; ++q) {
            float4 a = *(const float4*)(srcx + q * 4);
            float4 c = *(const float4*)(srcf + q * 4);
            int cb = p * 32 + q * 4;
            Sx[r * 257 + cb] = a.x; Sx[r * 257 + cb + 1] = a.y;
            Sx[r * 257 + cb + 2] = a.z; Sx[r * 257 + cb + 3] = a.w;
            Sf[r * 257 + cb] = c.x; Sf[r * 257 + cb + 1] = c.y;
            Sf[r * 257 + cb + 2] = c.z; Sf[r * 257 + cb + 3] = c.w;
        }
    }
    __syncthreads();
    {
        int r = tid >> 3, p = tid & 7;
        float l0 = 0.f, l1 = 0.f;
#pragma unroll
        for (int cc = 0; cc < 32; ++cc) {
            int c = p * 32 + cc;
            float xv = Sx[r * 257 + c], fv = Sf[r * 257 + c];
            l0 = fmaf(xv, Wsh[c], fmaf(fv, Wsh[256 + c], l0));
            l1 = fmaf(xv, Wsh[512 + c], fmaf(fv, Wsh[768 + c], l1));
        }
#pragma unroll
        for (int o = 4; o; o >>= 1) {
            l0 += __shfl_down_sync(0xffffffffu, l0, o, 8);
            l1 += __shfl_down_sync(0xffffffffu, l1, o, 8);
        }
        if (p == 0) {
            float m = fmaxf(l0, l1);
            float e0 = expf(l0 - m), e1 = expf(l1 - m);
            float inv = 1.f / (e0 + e1);
            W0[r] = e0 * inv; W1[r] = e1 * inv;
        }
    }
    __syncthreads();
    {
        int nl = tid & 31, cg = tid >> 5;
        float w0 = W0[nl], w1 = W1[nl];
        float* o0 = out + (size_t)b * CC * NN;
        float* o1 = out + (size_t)BB * CC * NN + (size_t)b * CC * NN;
#pragma unroll
        for (int cc = 0; cc < 32; ++cc) {
            int c = cg * 32 + cc;
            float xv = Sx[nl * 257 + c], fv = Sf[nl * 257 + c];
            o0[(size_t)c * NN + n0 + nl] = fmaf(xv, w0, fv * w1);
            o1[(size_t)c * NN + n0 + nl] = fv;
        }
    }
}

// ---------------------------------------------------------------------------
extern "C" void kernel_launch(void* const* d_in, const int* in_sizes, int n_in,
                              void* d_out, int out_size) {
    const float* x = (const float*)d_in[0];
    const float* W = (const float*)d_in[1];
    float* out = (float*)d_out;

    cudaFuncSetAttribute(simargmax_kernel,
                         cudaFuncAttributeMaxDynamicSharedMemorySize, SMEM_TOTAL);
    cudaFuncSetAttribute(fuse_kernel,
                         cudaFuncAttributeMaxDynamicSharedMemorySize, FS_TOTAL);

    prep_kernel<<<dim3(NN / 32, BB), 256>>>(x);
    simargmax_kernel<<<dim3(16, BB), 256, SMEM_TOTAL>>>();
    fuse_kernel<<<dim3(NN / 32, BB), 256, FS_TOTAL>>>(W, out);
}

// round 8
// speedup vs baseline: 1.2327x; 1.2327x over previous
#include <cuda_runtime.h>
#include <cuda_fp16.h>
#include <math.h>
#include <stdint.h>

#define BB 8
#define CC 256
#define NN 2048

// rn-scaled 2-way fp16 splits, K-contiguous: g_xs[b][n][s*256 + c], s in {0,1}
__device__ __align__(16) __half g_xs[(size_t)BB * NN * 512];
// transposed f32 copy for fuse gathers: g_xt[b][n][c]
__device__ __align__(16) float g_xt[(size_t)BB * NN * CC];
// packed (sortable-value, ~j) per token; zero-init; atomicMax-merged
__device__ unsigned long long g_key[BB * NN];

// ---------------------------------------------------------------------------
// prep: per token compute rn, write f32 transpose (g_xt) and rn-scaled 2-way
// fp16 splits (g_xs). grid (NN/32, BB), 256 threads.
// ---------------------------------------------------------------------------
__global__ __launch_bounds__(256) void prep_kernel(const float* __restrict__ x) {
    __shared__ __half S[32][520];
    __shared__ float nsum[32][8];
    __shared__ float rns[32];
    int b = blockIdx.y, n0 = blockIdx.x * 32;
    int tid = threadIdx.x, nl = tid & 31, c8 = tid >> 5;
    const float* xp = x + (size_t)b * CC * NN + n0 + nl;

    float v[32];
    float s = 0.f;
#pragma unroll
    for (int cc = 0; cc < 32; ++cc) {
        int c = c8 * 32 + cc;
        v[cc] = xp[(size_t)c * NN];
        s = fmaf(v[cc], v[cc], s);
    }
    nsum[nl][c8] = s;
    __syncthreads();
    if (tid < 32) {
        float t = 0.f;
#pragma unroll
        for (int q = 0; q < 8; ++q) t += nsum[tid][q];
        rns[tid] = rsqrtf(t + (float)CC * 1e-6f);
    }
    __syncthreads();
    float rn = rns[nl];

    float* xt = g_xt + ((size_t)(b * NN + n0 + nl)) * 256 + c8 * 32;
#pragma unroll
    for (int q = 0; q < 8; ++q)
        *(float4*)(xt + q * 4) = make_float4(v[q * 4], v[q * 4 + 1], v[q * 4 + 2], v[q * 4 + 3]);

#pragma unroll
    for (int cc = 0; cc < 32; ++cc) {
        int c = c8 * 32 + cc;
        float f = v[cc] * rn;
        __half h1 = __float2half_rn(f);
        float r1 = f - __half2float(h1);
        __half h2 = __float2half_rn(r1);
        S[nl][c] = h1; S[nl][256 + c] = h2;
    }
    __syncthreads();

    __half* outb = g_xs + ((size_t)(b * NN + n0)) * 512;
#pragma unroll
    for (int r = 0; r < 8; ++r) {
        int idx = tid + r * 256;
        int row = idx >> 6, c16 = idx & 63;
        uint4 val = *(const uint4*)&S[row][c16 * 8];
        *(uint4*)(outb + (size_t)row * 512 + c16 * 8) = val;
    }
}

// ---------------------------------------------------------------------------
// smem map for simargmax (byte offsets)
// ---------------------------------------------------------------------------
#define A0OFF  0                    // 128 rows x 32 chunks, stride 33 -> 67584
#define B0OFF  67584
#define STOFF  135168               // 3 ring slots x 18432 (128 rows, stride 9)
#define RVOFF  190464               // row merge val [128]
#define RJOFF  190976               // row merge idx [128]
#define CVOFF  191488               // col merge val [3][128]
#define CJOFF  193024               // col merge idx [3][128]
#define SMEM_TOTAL 194560

__device__ __forceinline__ void ldsm4(uint32_t* r, uint32_t saddr) {
    asm volatile("ldmatrix.sync.aligned.m8n8.x4.shared.b16 {%0,%1,%2,%3}, [%4];"
                 : "=r"(r[0]), "=r"(r[1]), "=r"(r[2]), "=r"(r[3]) : "r"(saddr));
}
__device__ __forceinline__ void mma16816f(float (&d)[4], const uint32_t (&a)[4],
                                          uint32_t b0, uint32_t b1) {
    asm volatile(
        "mma.sync.aligned.m16n8k16.row.col.f32.f16.f16.f32 "
        "{%0,%1,%2,%3},{%4,%5,%6,%7},{%8,%9},{%0,%1,%2,%3};"
        : "+f"(d[0]), "+f"(d[1]), "+f"(d[2]), "+f"(d[3])
        : "r"(a[0]), "r"(a[1]), "r"(a[2]), "r"(a[3]), "r"(b0), "r"(b1));
}
__device__ __forceinline__ void mma16816h(uint32_t (&d)[2], const uint32_t (&a)[4],
                                          uint32_t b0, uint32_t b1) {
    asm volatile(
        "mma.sync.aligned.m16n8k16.row.col.f16.f16.f16.f16 "
        "{%0,%1},{%2,%3,%4,%5},{%6,%7},{%0,%1};"
        : "+r"(d[0]), "+r"(d[1])
        : "r"(a[0]), "r"(a[1]), "r"(a[2]), "r"(a[3]), "r"(b0), "r"(b1));
}

__device__ __forceinline__ unsigned long long packKey(float v, int idx) {
    uint32_t u = __float_as_uint(v);
    uint32_t key = (u & 0x80000000u) ? ~u : (u | 0x80000000u);
    return ((unsigned long long)key << 32) | (uint32_t)(0xFFFFFFFFu - (uint32_t)idx);
}

// copy one split-0 resident block (128 rows x 256 halves), padded stride 33
__device__ __forceinline__ void cpRes(uint32_t smb, uint32_t off,
                                      const __half* xsb, int r0, int tid) {
#pragma unroll
    for (int q = 0; q < 16; ++q) {
        int idx = tid + q * 256;
        int row = idx >> 5, ch = idx & 31;
        uint32_t sa = smb + off + ((row * 33 + ch) << 4);
        const void* ga = xsb + (size_t)(r0 + row) * 512 + ch * 8;
        asm volatile("cp.async.cg.shared.global [%0], [%1], 16;" :: "r"(sa), "l"(ga));
    }
}
// streamed split-1 tile t: t<4 -> A1 kc=t (i-block); t>=4 -> B1 kc=t-4 (j-block)
__device__ __forceinline__ void cpT(uint32_t smb, const __half* xsb, int t,
                                    int i0, int j0, int tid) {
    int kc = t & 3;
    int base = (t < 4) ? i0 : j0;
    int slot = t % 3;
#pragma unroll
    for (int q = 0; q < 4; ++q) {
        int idx = tid + q * 256;
        int row = idx >> 3, ch = idx & 7;
        uint32_t sa = smb + STOFF + slot * 18432 + ((row * 9 + ch) << 4);
        const void* ga = xsb + (size_t)(base + row) * 512 + 256 + kc * 64 + ch * 8;
        asm volatile("cp.async.cg.shared.global [%0], [%1], 16;" :: "r"(sa), "l"(ga));
    }
}
#define CP_COMMIT() asm volatile("cp.async.commit_group;" ::: "memory")

// ---------------------------------------------------------------------------
// simargmax (triangular): tile (it<=jt). P0=(A0,B0) f32, P1=(A1,B0) f16,
// P2=(A0,B1) f16. Row-max for i-block + col-max for j-block, atomicMax-merged.
// grid (136, BB), 256 threads (4M x 2N warps).
// ---------------------------------------------------------------------------
__global__ __launch_bounds__(256, 1) void simargmax_kernel() {
    extern __shared__ __align__(1024) char sm[];
    const int b = blockIdx.y;
    int p = blockIdx.x, it = 0, rem = 16;
    while (p >= rem) { p -= rem; ++it; --rem; }
    const int jt = it + p;
    const int i0 = it * 128, j0 = jt * 128;
    const bool diag = (it == jt);

    const int tid = threadIdx.x, lane = tid & 31, wid = tid >> 5;
    const int wm = wid >> 1, wn = wid & 1;
    const uint32_t smb = (uint32_t)__cvta_generic_to_shared(sm);
    const __half* xsb = g_xs + (size_t)b * NN * 512;

    // residents (group 0), then stream tiles 0,1
    cpRes(smb, A0OFF, xsb, i0, tid);
    cpRes(smb, B0OFF, xsb, j0, tid);
    CP_COMMIT();
    cpT(smb, xsb, 0, i0, j0, tid); CP_COMMIT();
    cpT(smb, xsb, 1, i0, j0, tid); CP_COMMIT();

    const int ar0 = wm * 32 + (lane & 15);
    const int akh = lane >> 4;
    const int jr0 = wn * 64 + ((lane >> 4) & 1) * 8 + (lane & 7);
    const int bkh = (lane >> 3) & 1;

    float    acc[2][8][4];
    uint32_t accH[2][8][2];
#pragma unroll
    for (int mt = 0; mt < 2; ++mt)
#pragma unroll
        for (int nt = 0; nt < 8; ++nt) {
#pragma unroll
            for (int rr = 0; rr < 4; ++rr) acc[mt][nt][rr] = 0.f;
            accH[mt][nt][0] = 0u; accH[mt][nt][1] = 0u;
        }

    asm volatile("cp.async.wait_group 2;" ::: "memory");   // residents ready
    __syncthreads();

    // ---- P0: (A0, B0) -> f32 acc, K=256 resident ----
    for (int kc = 0; kc < 4; ++kc) {
#pragma unroll
        for (int ks = 0; ks < 4; ++ks) {
            const int cb = kc * 8 + ks * 2;
            uint32_t bf[4][4];
#pragma unroll
            for (int ntp = 0; ntp < 4; ++ntp)
                ldsm4(bf[ntp], smb + B0OFF + ((((jr0 + ntp * 16) * 33) + cb + bkh) << 4));
            uint32_t a0[2][4];
#pragma unroll
            for (int mt = 0; mt < 2; ++mt)
                ldsm4(a0[mt], smb + A0OFF + ((((ar0 + mt * 16) * 33) + cb + akh) << 4));
#pragma unroll
            for (int ntp = 0; ntp < 4; ++ntp) {
                mma16816f(acc[0][ntp * 2],     a0[0], bf[ntp][0], bf[ntp][1]);
                mma16816f(acc[0][ntp * 2 + 1], a0[0], bf[ntp][2], bf[ntp][3]);
                mma16816f(acc[1][ntp * 2],     a0[1], bf[ntp][0], bf[ntp][1]);
                mma16816f(acc[1][ntp * 2 + 1], a0[1], bf[ntp][2], bf[ntp][3]);
            }
        }
    }

    // ---- P1/P2: streamed split-1 tiles, f16 acc ----
    for (int t = 0; t < 8; ++t) {
        const int kc = t & 3;
        const int slot = t % 3;
        asm volatile("cp.async.wait_group 1;" ::: "memory");   // tile t ready
        __syncthreads();                                       // slot reuse safe
        if (t + 2 < 8) cpT(smb, xsb, t + 2, i0, j0, tid);
        CP_COMMIT();

        if (t < 4) {
            // P1: A1 (stream) x B0 (resident)
#pragma unroll
            for (int ks = 0; ks < 4; ++ks) {
                const int cb = kc * 8 + ks * 2;
                uint32_t bf[4][4];
#pragma unroll
                for (int ntp = 0; ntp < 4; ++ntp)
                    ldsm4(bf[ntp], smb + B0OFF + ((((jr0 + ntp * 16) * 33) + cb + bkh) << 4));
                uint32_t a1[2][4];
#pragma unroll
                for (int mt = 0; mt < 2; ++mt)
                    ldsm4(a1[mt], smb + STOFF + slot * 18432 +
                                  ((((ar0 + mt * 16) * 9) + ks * 2 + akh) << 4));
#pragma unroll
                for (int ntp = 0; ntp < 4; ++ntp) {
                    mma16816h(accH[0][ntp * 2],     a1[0], bf[ntp][0], bf[ntp][1]);
                    mma16816h(accH[0][ntp * 2 + 1], a1[0], bf[ntp][2], bf[ntp][3]);
                    mma16816h(accH[1][ntp * 2],     a1[1], bf[ntp][0], bf[ntp][1]);
                    mma16816h(accH[1][ntp * 2 + 1], a1[1], bf[ntp][2], bf[ntp][3]);
                }
            }
        } else {
            // P2: A0 (resident) x B1 (stream)
#pragma unroll
            for (int ks = 0; ks < 4; ++ks) {
                const int cb = kc * 8 + ks * 2;
                uint32_t bf[4][4];
#pragma unroll
                for (int ntp = 0; ntp < 4; ++ntp)
                    ldsm4(bf[ntp], smb + STOFF + slot * 18432 +
                                   ((((jr0 + ntp * 16) * 9) + ks * 2 + bkh) << 4));
                uint32_t a0[2][4];
#pragma unroll
                for (int mt = 0; mt < 2; ++mt)
                    ldsm4(a0[mt], smb + A0OFF + ((((ar0 + mt * 16) * 33) + cb + akh) << 4));
#pragma unroll
                for (int ntp = 0; ntp < 4; ++ntp) {
                    mma16816h(accH[0][ntp * 2],     a0[0], bf[ntp][0], bf[ntp][1]);
                    mma16816h(accH[0][ntp * 2 + 1], a0[0], bf[ntp][2], bf[ntp][3]);
                    mma16816h(accH[1][ntp * 2],     a0[1], bf[ntp][0], bf[ntp][1]);
                    mma16816h(accH[1][ntp * 2 + 1], a0[1], bf[ntp][2], bf[ntp][3]);
                }
            }
        }
    }

    // ---- epilogue: row-max (i-block) + col-max (j-block) ----
    const float NEG = __int_as_float(0xff800000);
    float best[4]; int bidx[4];
#pragma unroll
    for (int s = 0; s < 4; ++s) { best[s] = NEG; bidx[s] = 0; }
    float cbv[16]; int cbi[16];
#pragma unroll
    for (int s = 0; s < 16; ++s) { cbv[s] = NEG; cbi[s] = 0; }

#pragma unroll
    for (int mt = 0; mt < 2; ++mt)
#pragma unroll
        for (int nt = 0; nt < 8; ++nt)
#pragma unroll
            for (int rr = 0; rr < 4; ++rr) {
                int jl = wn * 64 + nt * 8 + (lane & 3) * 2 + (rr & 1);
                int il = wm * 32 + mt * 16 + (rr >> 1) * 8 + (lane >> 2);
                __half2 h2 = *(__half2*)&accH[mt][nt][rr >> 1];
                float cross = (rr & 1) ? __high2float(h2) : __low2float(h2);
                float v = acc[mt][nt][rr] + cross;
                if (diag && il == jl) v = NEG;
                int slot = mt * 2 + (rr >> 1);
                if (v > best[slot]) { best[slot] = v; bidx[slot] = jl; }   // jl asc
                int ci = nt * 2 + (rr & 1);
                if (v > cbv[ci]) { cbv[ci] = v; cbi[ci] = il; }            // il asc
            }

    float* Rv = (float*)(sm + RVOFF);  int* Rj = (int*)(sm + RJOFF);
    float* Cv = (float*)(sm + CVOFF);  int* Cj = (int*)(sm + CJOFF);

    // row: reduce over lane&3 partners (xor 1,2)
#pragma unroll
    for (int slot = 0; slot < 4; ++slot) {
        float v = best[slot]; int j = bidx[slot];
#pragma unroll
        for (int o = 1; o <= 2; o <<= 1) {
            float vo = __shfl_xor_sync(0xffffffffu, v, o);
            int   jo = __shfl_xor_sync(0xffffffffu, j, o);
            if (vo > v || (vo == v && jo < j)) { v = vo; j = jo; }
        }
        best[slot] = v; bidx[slot] = j;
        int row = wm * 32 + (slot >> 1) * 16 + (slot & 1) * 8 + (lane >> 2);
        if (wn == 1 && (lane & 3) == 0) { Rv[row] = v; Rj[row] = j; }
    }
    // col: reduce over lane>>2 partners (xor 4,8,16)
#pragma unroll
    for (int ci = 0; ci < 16; ++ci) {
        float v = cbv[ci]; int i = cbi[ci];
#pragma unroll
        for (int o = 4; o <= 16; o <<= 1) {
            float vo = __shfl_xor_sync(0xffffffffu, v, o);
            int   io = __shfl_xor_sync(0xffffffffu, i, o);
            if (vo > v || (vo == v && io < i)) { v = vo; i = io; }
        }
        cbv[ci] = v; cbi[ci] = i;
        if (!diag && wm > 0 && lane < 4) {
            int col = wn * 64 + (ci >> 1) * 8 + lane * 2 + (ci & 1);
            Cv[(wm - 1) * 128 + col] = v;
            Cj[(wm - 1) * 128 + col] = i;
        }
    }
    __syncthreads();

    if (wn == 0 && (lane & 3) == 0) {
#pragma unroll
        for (int slot = 0; slot < 4; ++slot) {
            int row = wm * 32 + (slot >> 1) * 16 + (slot & 1) * 8 + (lane >> 2);
            float v = best[slot]; int j = bidx[slot];
            float vo = Rv[row]; int jo = Rj[row];
            if (vo > v || (vo == v && jo < j)) { v = vo; j = jo; }
            atomicMax(&g_key[b * NN + i0 + row], packKey(v, j0 + j));
        }
    }
    if (!diag && wm == 0 && lane < 4) {
#pragma unroll
        for (int ci = 0; ci < 16; ++ci) {
            int col = wn * 64 + (ci >> 1) * 8 + lane * 2 + (ci & 1);
            float v = cbv[ci]; int i = cbi[ci];
#pragma unroll
            for (int w = 0; w < 3; ++w) {
                float vo = Cv[w * 128 + col];
                int   io = Cj[w * 128 + col];
                if (vo > v || (vo == v && io < i)) { v = vo; i = io; }
            }
            atomicMax(&g_key[b * NN + j0 + col], packKey(v, i0 + i));
        }
    }
}

// ---------------------------------------------------------------------------
// fuse: staged in smem via g_xt; coalesced reads/writes. grid (NN/32, BB), 256 thr.
// ---------------------------------------------------------------------------
#define FS_SF 32896
#define FS_W  65792
#define FS_JI 69888
#define FS_W0 70016
#define FS_W1 70144
#define FS_TOTAL 70272

__global__ __launch_bounds__(256) void fuse_kernel(const float* __restrict__ W,
                                                   float* __restrict__ out) {
    extern __shared__ char fsm[];
    float* Sx  = (float*)fsm;
    float* Sf  = (float*)(fsm + FS_SF);
    float* Wsh = (float*)(fsm + FS_W);
    int*   Ji  = (int*)(fsm + FS_JI);
    float* W0  = (float*)(fsm + FS_W0);
    float* W1  = (float*)(fsm + FS_W1);

    int b = blockIdx.y, n0 = blockIdx.x * 32, tid = threadIdx.x;
    for (int e = tid; e < 1024; e += 256) Wsh[e] = W[e];
    if (tid < 32) {
        unsigned long long k = g_key[b * NN + n0 + tid];
        Ji[tid] = (int)(0xFFFFFFFFu - (uint32_t)(k & 0xFFFFFFFFu));
    }
    __syncthreads();

    const float* xtb = g_xt + (size_t)b * NN * 256;
    {
        int r = tid >> 3, p = tid & 7;
        const float* srcx = xtb + (size_t)(n0 + r) * 256 + p * 32;
        const float* srcf = xtb + (size_t)Ji[r] * 256 + p * 32;
#pragma unroll
        for (int q = 0; q < 8; ++q) {
            float4 a = *(const float4*)(srcx + q * 4);
            float4 c = *(const float4*)(srcf + q * 4);
            int cb = p * 32 + q * 4;
            Sx[r * 257 + cb] = a.x; Sx[r * 257 + cb + 1] = a.y;
            Sx[r * 257 + cb + 2] = a.z; Sx[r * 257 + cb + 3] = a.w;
            Sf[r * 257 + cb] = c.x; Sf[r * 257 + cb + 1] = c.y;
            Sf[r * 257 + cb + 2] = c.z; Sf[r * 257 + cb + 3] = c.w;
        }
    }
    __syncthreads();
    {
        int r = tid >> 3, p = tid & 7;
        float l0 = 0.f, l1 = 0.f;
#pragma unroll
        for (int cc = 0; cc < 32; ++cc) {
            int c = p * 32 + cc;
            float xv = Sx[r * 257 + c], fv = Sf[r * 257 + c];
            l0 = fmaf(xv, Wsh[c], fmaf(fv, Wsh[256 + c], l0));
            l1 = fmaf(xv, Wsh[512 + c], fmaf(fv, Wsh[768 + c], l1));
        }
#pragma unroll
        for (int o = 4; o; o >>= 1) {
            l0 += __shfl_down_sync(0xffffffffu, l0, o, 8);
            l1 += __shfl_down_sync(0xffffffffu, l1, o, 8);
        }
        if (p == 0) {
            float m = fmaxf(l0, l1);
            float e0 = expf(l0 - m), e1 = expf(l1 - m);
            float inv = 1.f / (e0 + e1);
            W0[r] = e0 * inv; W1[r] = e1 * inv;
        }
    }
    __syncthreads();
    {
        int nl = tid & 31, cg = tid >> 5;
        float w0 = W0[nl], w1 = W1[nl];
        float* o0 = out + (size_t)b * CC * NN;
        float* o1 = out + (size_t)BB * CC * NN + (size_t)b * CC * NN;
#pragma unroll
        for (int cc = 0; cc < 32; ++cc) {
            int c = cg * 32 + cc;
            float xv = Sx[nl * 257 + c], fv = Sf[nl * 257 + c];
            o0[(size_t)c * NN + n0 + nl] = fmaf(xv, w0, fv * w1);
            o1[(size_t)c * NN + n0 + nl] = fv;
        }
    }
}

// ---------------------------------------------------------------------------
extern "C" void kernel_launch(void* const* d_in, const int* in_sizes, int n_in,
                              void* d_out, int out_size) {
    const float* x = (const float*)d_in[0];
    const float* W = (const float*)d_in[1];
    float* out = (float*)d_out;

    cudaFuncSetAttribute(simargmax_kernel,
                         cudaFuncAttributeMaxDynamicSharedMemorySize, SMEM_TOTAL);
    cudaFuncSetAttribute(fuse_kernel,
                         cudaFuncAttributeMaxDynamicSharedMemorySize, FS_TOTAL);

    prep_kernel<<<dim3(NN / 32, BB), 256>>>(x);
    simargmax_kernel<<<dim3(136, BB), 256, SMEM_TOTAL>>>();
    fuse_kernel<<<dim3(NN / 32, BB), 256, FS_TOTAL>>>(W, out);
}